// round 1
// baseline (speedup 1.0000x reference)
#include <cuda_runtime.h>
#include <math.h>

#define B   8
#define LQ  1024
#define LK  1024
#define DD  512
#define H   8
#define DKV 64   // DK == DV == 64

// Scratch (static device globals — allocation-guard safe)
__device__ float g_q[B*H*LQ*DKV];     // 16 MB
__device__ float g_k[B*H*LK*DKV];     // 16 MB
__device__ float g_v[B*H*LK*DKV];     // 16 MB
__device__ float g_conc[B*LQ*H*DKV];  // 16 MB

// ---------------------------------------------------------------------------
// Projection: out[b,h,l,e] = sum_d X[b,l,d] * W[h,d,e]
// grid (L/64, H, B), 256 threads, 64x64 output tile, 4x4 per thread
// which: 0->g_q, 1->g_k, 2->g_v
// ---------------------------------------------------------------------------
__global__ __launch_bounds__(256) void proj_kernel(
    const float* __restrict__ X, const float* __restrict__ W, int which, int L)
{
    float* out = (which == 0) ? g_q : (which == 1) ? g_k : g_v;

    const int l0  = blockIdx.x * 64;
    const int h   = blockIdx.y;
    const int b   = blockIdx.z;
    const int tid = threadIdx.x;
    const int ty  = tid >> 4;
    const int tx  = tid & 15;

    __shared__ float sA[64 * 64];  // [d][l]  (transposed)
    __shared__ float sB[64 * 64];  // [d][e]

    float acc[4][4];
#pragma unroll
    for (int i = 0; i < 4; ++i)
#pragma unroll
        for (int j = 0; j < 4; ++j) acc[i][j] = 0.f;

    const float* Xb = X + ((size_t)b * L + l0) * DD;
    const float* Wh = W + (size_t)h * DD * 64;

    for (int dt = 0; dt < DD / 64; ++dt) {
        __syncthreads();
        // Load X tile transposed: sA[d][l]
#pragma unroll
        for (int r = 0; r < 4; ++r) {
            int u   = tid + r * 256;   // 0..1023 float4 units
            int row = u >> 4;          // l
            int c4  = u & 15;          // d/4
            float4 v = *(const float4*)(Xb + (size_t)row * DD + dt * 64 + c4 * 4);
            sA[(c4 * 4 + 0) * 64 + row] = v.x;
            sA[(c4 * 4 + 1) * 64 + row] = v.y;
            sA[(c4 * 4 + 2) * 64 + row] = v.z;
            sA[(c4 * 4 + 3) * 64 + row] = v.w;
        }
        // Load W tile natural: sB[d][e]
#pragma unroll
        for (int r = 0; r < 4; ++r) {
            int u   = tid + r * 256;
            int row = u >> 4;          // d within tile
            int c4  = u & 15;          // e/4
            *(float4*)(sB + row * 64 + c4 * 4) =
                *(const float4*)(Wh + (size_t)(dt * 64 + row) * 64 + c4 * 4);
        }
        __syncthreads();
#pragma unroll
        for (int kk = 0; kk < 64; ++kk) {
            float4 a  = *(const float4*)(sA + kk * 64 + ty * 4);
            float4 bb = *(const float4*)(sB + kk * 64 + tx * 4);
            float av[4] = {a.x, a.y, a.z, a.w};
            float bv[4] = {bb.x, bb.y, bb.z, bb.w};
#pragma unroll
            for (int i = 0; i < 4; ++i)
#pragma unroll
                for (int j = 0; j < 4; ++j) acc[i][j] += av[i] * bv[j];
        }
    }

    float* ob = out + (((size_t)b * H + h) * L + l0) * 64;
#pragma unroll
    for (int i = 0; i < 4; ++i) {
        float4 v = make_float4(acc[i][0], acc[i][1], acc[i][2], acc[i][3]);
        *(float4*)(ob + (size_t)(ty * 4 + i) * 64 + tx * 4) = v;
    }
}

// ---------------------------------------------------------------------------
// Fused flash attention per (b,h,q-tile of 64)
// grid (LQ/64, B*H), 256 threads
// smem: sQ[d][i] | sK[d][j] | sV[j][e] | sPT[j][i] | mask[64]
// ---------------------------------------------------------------------------
__global__ __launch_bounds__(256) void attn_kernel(const float* __restrict__ mask)
{
    extern __shared__ float sm[];
    float* sQ    = sm;           // 4096
    float* sK    = sm + 4096;    // 4096
    float* sV    = sm + 8192;    // 4096
    float* sPT   = sm + 12288;   // 4096
    float* smask = sm + 16384;   // 64

    const int q0  = blockIdx.x * 64;
    const int bh  = blockIdx.y;
    const int b   = bh >> 3;     // H = 8
    const int h   = bh & 7;
    const int tid = threadIdx.x;
    const int ty  = tid >> 4;
    const int tx  = tid & 15;

    const float* Qb = g_q + ((size_t)bh * LQ + q0) * 64;
    const float* Kb = g_k + (size_t)bh * LK * 64;
    const float* Vb = g_v + (size_t)bh * LK * 64;

    // Load Q tile transposed: sQ[d][i]
#pragma unroll
    for (int r = 0; r < 4; ++r) {
        int u   = tid + r * 256;
        int row = u >> 4;
        int c4  = u & 15;
        float4 v = *(const float4*)(Qb + (size_t)row * 64 + c4 * 4);
        sQ[(c4 * 4 + 0) * 64 + row] = v.x;
        sQ[(c4 * 4 + 1) * 64 + row] = v.y;
        sQ[(c4 * 4 + 2) * 64 + row] = v.z;
        sQ[(c4 * 4 + 3) * 64 + row] = v.w;
    }

    float m[4], l[4], o[4][4];
#pragma unroll
    for (int i = 0; i < 4; ++i) {
        m[i] = -1e30f;
        l[i] = 0.f;
#pragma unroll
        for (int j = 0; j < 4; ++j) o[i][j] = 0.f;
    }

    for (int kt = 0; kt < LK / 64; ++kt) {
        __syncthreads();  // guard prior-iter smem reads
        // K tile transposed: sK[d][j]
#pragma unroll
        for (int r = 0; r < 4; ++r) {
            int u   = tid + r * 256;
            int row = u >> 4;
            int c4  = u & 15;
            float4 v = *(const float4*)(Kb + (size_t)(kt * 64 + row) * 64 + c4 * 4);
            sK[(c4 * 4 + 0) * 64 + row] = v.x;
            sK[(c4 * 4 + 1) * 64 + row] = v.y;
            sK[(c4 * 4 + 2) * 64 + row] = v.z;
            sK[(c4 * 4 + 3) * 64 + row] = v.w;
        }
        // V tile natural: sV[j][e]
#pragma unroll
        for (int r = 0; r < 4; ++r) {
            int u   = tid + r * 256;
            int row = u >> 4;
            int c4  = u & 15;
            *(float4*)(sV + row * 64 + c4 * 4) =
                *(const float4*)(Vb + (size_t)(kt * 64 + row) * 64 + c4 * 4);
        }
        if (tid < 64) smask[tid] = mask[(size_t)b * LK + kt * 64 + tid];
        __syncthreads();

        // S = Q K^T (4x4 per thread), K-dim = 64
        float s[4][4];
#pragma unroll
        for (int i = 0; i < 4; ++i)
#pragma unroll
            for (int j = 0; j < 4; ++j) s[i][j] = 0.f;
#pragma unroll
        for (int kk = 0; kk < 64; ++kk) {
            float4 a  = *(const float4*)(sQ + kk * 64 + ty * 4);
            float4 bb = *(const float4*)(sK + kk * 64 + tx * 4);
            float av[4] = {a.x, a.y, a.z, a.w};
            float bv[4] = {bb.x, bb.y, bb.z, bb.w};
#pragma unroll
            for (int i = 0; i < 4; ++i)
#pragma unroll
                for (int j = 0; j < 4; ++j) s[i][j] += av[i] * bv[j];
        }

        // mask (per key column)
#pragma unroll
        for (int j = 0; j < 4; ++j) {
            if (smask[tx * 4 + j] == 0.f) {
                s[0][j] = -1e30f; s[1][j] = -1e30f;
                s[2][j] = -1e30f; s[3][j] = -1e30f;
            }
        }

        // online softmax per row (16 lanes per row group share via shuffle)
#pragma unroll
        for (int i = 0; i < 4; ++i) {
            float rm = fmaxf(fmaxf(s[i][0], s[i][1]), fmaxf(s[i][2], s[i][3]));
#pragma unroll
            for (int off = 8; off >= 1; off >>= 1)
                rm = fmaxf(rm, __shfl_xor_sync(0xffffffffu, rm, off));
            float mn = fmaxf(m[i], rm);
            float sc = __expf(m[i] - mn);
            float rs = 0.f;
#pragma unroll
            for (int j = 0; j < 4; ++j) {
                s[i][j] = __expf(s[i][j] - mn);
                rs += s[i][j];
            }
#pragma unroll
            for (int off = 8; off >= 1; off >>= 1)
                rs += __shfl_xor_sync(0xffffffffu, rs, off);
            l[i] = l[i] * sc + rs;
            m[i] = mn;
#pragma unroll
            for (int j = 0; j < 4; ++j) o[i][j] *= sc;
        }

        // stage P transposed: sPT[j][i]
#pragma unroll
        for (int j = 0; j < 4; ++j) {
            float4 v = make_float4(s[0][j], s[1][j], s[2][j], s[3][j]);
            *(float4*)(sPT + (size_t)(tx * 4 + j) * 64 + ty * 4) = v;
        }
        __syncthreads();

        // O += P V  (inner over 64 keys)
#pragma unroll
        for (int kk = 0; kk < 64; ++kk) {
            float4 a  = *(const float4*)(sPT + kk * 64 + ty * 4);
            float4 bb = *(const float4*)(sV + kk * 64 + tx * 4);
            float av[4] = {a.x, a.y, a.z, a.w};
            float bv[4] = {bb.x, bb.y, bb.z, bb.w};
#pragma unroll
            for (int i = 0; i < 4; ++i)
#pragma unroll
                for (int j = 0; j < 4; ++j) o[i][j] += av[i] * bv[j];
        }
    }

    // epilogue: normalize and write conc[b, q, h*64+e]
    float* cb = g_conc + ((size_t)b * LQ + q0) * (H * DKV) + h * 64;
#pragma unroll
    for (int i = 0; i < 4; ++i) {
        float inv = 1.f / l[i];
        float4 v = make_float4(o[i][0] * inv, o[i][1] * inv,
                               o[i][2] * inv, o[i][3] * inv);
        *(float4*)(cb + (size_t)(ty * 4 + i) * (H * DKV) + tx * 4) = v;
    }
}

// ---------------------------------------------------------------------------
// LayerNorm over last dim (512), one block (128 threads) per row
// ---------------------------------------------------------------------------
__global__ __launch_bounds__(128) void ln_kernel(
    const float* __restrict__ gamma, const float* __restrict__ beta,
    float* __restrict__ out)
{
    const int row = blockIdx.x;
    const float* x = g_conc + (size_t)row * 512;
    const int tid = threadIdx.x;

    float v[4];
    float s = 0.f;
#pragma unroll
    for (int i = 0; i < 4; ++i) { v[i] = x[tid + i * 128]; s += v[i]; }

    __shared__ float red1[4];
    __shared__ float red2[4];
#pragma unroll
    for (int off = 16; off >= 1; off >>= 1)
        s += __shfl_xor_sync(0xffffffffu, s, off);
    if ((tid & 31) == 0) red1[tid >> 5] = s;
    __syncthreads();
    float mean = (red1[0] + red1[1] + red1[2] + red1[3]) * (1.f / 512.f);

    float q = 0.f;
#pragma unroll
    for (int i = 0; i < 4; ++i) { float d = v[i] - mean; q += d * d; }
#pragma unroll
    for (int off = 16; off >= 1; off >>= 1)
        q += __shfl_xor_sync(0xffffffffu, q, off);
    if ((tid & 31) == 0) red2[tid >> 5] = q;
    __syncthreads();
    float var  = (red2[0] + red2[1] + red2[2] + red2[3]) * (1.f / 512.f);
    float rstd = rsqrtf(var + 1e-14f);
    float g = gamma[0], be = beta[0];
#pragma unroll
    for (int i = 0; i < 4; ++i)
        out[(size_t)row * 512 + tid + i * 128] = (v[i] - mean) * rstd * g + be;
}

// ---------------------------------------------------------------------------
extern "C" void kernel_launch(void* const* d_in, const int* in_sizes, int n_in,
                              void* d_out, int out_size)
{
    const float* query = (const float*)d_in[0];
    const float* key_t = (const float*)d_in[1];
    const float* value = (const float*)d_in[2];
    const float* mask  = (const float*)d_in[3];
    const float* Wq    = (const float*)d_in[4];
    const float* Wk    = (const float*)d_in[5];
    const float* Wv    = (const float*)d_in[6];
    const float* gamma = (const float*)d_in[7];
    const float* beta  = (const float*)d_in[8];
    float* out = (float*)d_out;

    dim3 pg(LQ / 64, H, B);
    proj_kernel<<<pg, 256>>>(query, Wq, 0, LQ);
    proj_kernel<<<pg, 256>>>(key_t, Wk, 1, LK);
    proj_kernel<<<pg, 256>>>(value, Wv, 2, LK);

    const int attn_smem = (4 * 4096 + 64) * (int)sizeof(float);  // 65792 B
    static int smem_set = 0;
    if (!smem_set) {
        cudaFuncSetAttribute(attn_kernel,
                             cudaFuncAttributeMaxDynamicSharedMemorySize,
                             attn_smem);
        smem_set = 1;
    }
    attn_kernel<<<dim3(LQ / 64, B * H), 256, attn_smem>>>(mask);

    ln_kernel<<<B * LQ, 128>>>(gamma, beta, out);
}